// round 1
// baseline (speedup 1.0000x reference)
#include <cuda_runtime.h>
#include <math.h>

// ---------------------------------------------------------------------------
// AreaAttention fused pipeline, fp32 baseline.
// Stages:
//  1) gemm_bnsilu : qk = silu(bn(qk_w @ x))          -> g_qk  [B,1024,N]
//  2) gemm_bnsilu : v  = silu(bn(v_w  @ x))          -> g_v   [B, 512,N]
//  3) conv3x3     : pp = silu(bn(conv3x3(v, pe_w)))  -> g_pp  [B, 512,N]
//  4) attn        : flash attention per (area-batch, head) -> g_ao [B,512,N]
//  5) gemm_bnsilu : y  = silu(bn(pr_w @ (ao + pp)))  -> d_out
// ---------------------------------------------------------------------------

#define Bc 8
#define Cc 512
#define Nc 4096     // H*W
#define HH 64
#define WW 64

__device__ float g_qk[33554432];   // 8*1024*4096
__device__ float g_v [16777216];   // 8*512*4096
__device__ float g_pp[16777216];
__device__ float g_ao[16777216];

__device__ __forceinline__ float silu_f(float y) {
    return y / (1.0f + __expf(-y));
}

// ---------------------------------------------------------------------------
// GEMM + BN + SiLU:   out[b,o,n] = silu(bn( sum_c W[o,c] * (X[b,c,n] + X2?) ))
// Block tile 64(O) x 64(N), k-tile 16, 256 threads, 4x4 microtile.
// ---------------------------------------------------------------------------
__global__ __launch_bounds__(256) void gemm_bnsilu(
    const float* __restrict__ W, const float* __restrict__ X,
    const float* __restrict__ X2,
    const float* __restrict__ gg, const float* __restrict__ bb,
    const float* __restrict__ rm, const float* __restrict__ rv,
    float* __restrict__ out, int O, int C, int N)
{
    __shared__ float Ws[16][68];   // [c][o], padded
    __shared__ float Xs[16][64];   // [c][n]

    const int tid = threadIdx.x;
    const int tx = tid & 15, ty = tid >> 4;
    const int b  = blockIdx.z;
    const int o0 = blockIdx.y * 64;
    const int n0 = blockIdx.x * 64;

    const float* Xb  = X  + (size_t)b * C * N;
    const float* X2b = X2 ? (X2 + (size_t)b * C * N) : nullptr;

    float acc[4][4] = {};

    const int wo = tid >> 2;           // 0..63  (o within tile)
    const int wc = (tid & 3) * 4;      // 0,4,8,12 (c base)
    const int xc = tid >> 4;           // 0..15 (c)
    const int xn = (tid & 15) * 4;     // n base

    for (int c0 = 0; c0 < C; c0 += 16) {
        float4 wv = *(const float4*)(W + (size_t)(o0 + wo) * C + c0 + wc);
        float4 xv = *(const float4*)(Xb + (size_t)(c0 + xc) * N + n0 + xn);
        if (X2b) {
            float4 x2 = *(const float4*)(X2b + (size_t)(c0 + xc) * N + n0 + xn);
            xv.x += x2.x; xv.y += x2.y; xv.z += x2.z; xv.w += x2.w;
        }
        __syncthreads();   // previous iter's compute done reading smem
        Ws[wc + 0][wo] = wv.x;
        Ws[wc + 1][wo] = wv.y;
        Ws[wc + 2][wo] = wv.z;
        Ws[wc + 3][wo] = wv.w;
        *(float4*)&Xs[xc][xn] = xv;
        __syncthreads();

        #pragma unroll
        for (int c = 0; c < 16; c++) {
            float4 av = *(const float4*)&Ws[c][ty * 4];
            float4 bv = *(const float4*)&Xs[c][tx * 4];
            float a[4] = {av.x, av.y, av.z, av.w};
            float d[4] = {bv.x, bv.y, bv.z, bv.w};
            #pragma unroll
            for (int i = 0; i < 4; i++)
                #pragma unroll
                for (int j = 0; j < 4; j++)
                    acc[i][j] += a[i] * d[j];
        }
    }

    // BN + SiLU epilogue
    float* ob = out + (size_t)b * O * N;
    #pragma unroll
    for (int i = 0; i < 4; i++) {
        const int oc = o0 + ty * 4 + i;
        const float sc = gg[oc] * rsqrtf(rv[oc] + 1e-5f);
        const float sh = bb[oc] - rm[oc] * sc;
        float4 r;
        r.x = silu_f(acc[i][0] * sc + sh);
        r.y = silu_f(acc[i][1] * sc + sh);
        r.z = silu_f(acc[i][2] * sc + sh);
        r.w = silu_f(acc[i][3] * sc + sh);
        *(float4*)(ob + (size_t)oc * N + n0 + tx * 4) = r;
    }
}

// ---------------------------------------------------------------------------
// conv3x3 (SAME) + BN + SiLU. Block = 64 output channels x one image row (64 px).
// Loops input channels in tiles of 8; 3-row x 66-col haloed input tile in smem.
// ---------------------------------------------------------------------------
__global__ __launch_bounds__(256) void conv3x3_bnsilu(
    const float* __restrict__ V, const float* __restrict__ W,
    const float* __restrict__ gg, const float* __restrict__ bb,
    const float* __restrict__ rm, const float* __restrict__ rv,
    float* __restrict__ out)
{
    __shared__ float WsS[8 * 9 * 64];   // [(c*9+tap)][o]
    __shared__ float InS[8][3][66];

    const int tid = threadIdx.x;
    const int tx = tid & 15, ty = tid >> 4;
    const int o0 = blockIdx.x * 64;
    const int h  = blockIdx.y;
    const int b  = blockIdx.z;

    const float* Vb = V + (size_t)b * Cc * Nc;
    float acc[4][4] = {};

    for (int c0 = 0; c0 < Cc; c0 += 8) {
        __syncthreads();
        // weights: W[o][c][tap] -> WsS[(c*9+tap)*64 + o]
        for (int t = tid; t < 8 * 9 * 64; t += 256) {
            const int o = t / 72;
            const int r = t % 72;            // r = c*9 + tap
            WsS[r * 64 + o] = W[(size_t)(o0 + o) * (Cc * 9) + (size_t)c0 * 9 + r];
        }
        // input halo rows h-1..h+1, cols -1..64
        for (int t = tid; t < 8 * 3 * 66; t += 256) {
            const int c  = t / 198;
            const int r2 = t % 198;
            const int r  = r2 / 66;
            const int col = r2 % 66;
            const int hh = h + r - 1;
            const int wcol = col - 1;
            float val = 0.0f;
            if (hh >= 0 && hh < HH && wcol >= 0 && wcol < WW)
                val = Vb[(size_t)(c0 + c) * Nc + hh * WW + wcol];
            InS[c][r][col] = val;
        }
        __syncthreads();

        #pragma unroll
        for (int c = 0; c < 8; c++) {
            float brow[3][6];
            #pragma unroll
            for (int r = 0; r < 3; r++)
                #pragma unroll
                for (int t2 = 0; t2 < 6; t2++)
                    brow[r][t2] = InS[c][r][tx * 4 + t2];

            #pragma unroll
            for (int tap = 0; tap < 9; tap++) {
                const int dh = tap / 3, dw = tap % 3;
                float4 av = *(const float4*)&WsS[(c * 9 + tap) * 64 + ty * 4];
                float a[4] = {av.x, av.y, av.z, av.w};
                #pragma unroll
                for (int i = 0; i < 4; i++)
                    #pragma unroll
                    for (int j = 0; j < 4; j++)
                        acc[i][j] += a[i] * brow[dh][j + dw];
            }
        }
    }

    float* ob = out + (size_t)b * Cc * Nc;
    #pragma unroll
    for (int i = 0; i < 4; i++) {
        const int oc = o0 + ty * 4 + i;
        const float sc = gg[oc] * rsqrtf(rv[oc] + 1e-5f);
        const float sh = bb[oc] - rm[oc] * sc;
        float4 r;
        r.x = silu_f(acc[i][0] * sc + sh);
        r.y = silu_f(acc[i][1] * sc + sh);
        r.z = silu_f(acc[i][2] * sc + sh);
        r.w = silu_f(acc[i][3] * sc + sh);
        *(float4*)(ob + (size_t)oc * Nc + h * WW + tx * 4) = r;
    }
}

// ---------------------------------------------------------------------------
// Flash attention. Grid (16 q-tiles, 256 bh). Block 256 threads.
// Per block: 64 queries, streams 16 K/V tiles of 64.
// Online softmax; accumulator in registers (4x4 per thread).
// ---------------------------------------------------------------------------
__global__ __launch_bounds__(256) void attn_kernel(
    const float* __restrict__ qk, const float* __restrict__ v,
    float* __restrict__ ao)
{
    extern __shared__ float sm[];
    float* Qs   = sm;             // [d][q]  64*64
    float* Ks   = Qs + 4096;      // [d][k]  64*64
    float* Vs   = Ks + 4096;      // [k][dv] 64*68
    float* Ps   = Vs + 4352;      // [k][q]  64*68
    float* mrow = Ps + 4352;      // 64
    float* lrow = mrow + 64;      // 64
    float* fac  = lrow + 64;      // 64
    float* red  = fac + 64;       // 4*64

    const int tid = threadIdx.x;
    const int tx = tid & 15, ty = tid >> 4;
    const int bh = blockIdx.y;
    const int head = bh & 7;
    const int ba = bh >> 3;
    const int b = ba >> 2;
    const int area = ba & 3;
    const int q0 = blockIdx.x * 64;
    const size_t nb = (size_t)area * 1024;

    const float* Qg = qk + ((size_t)b * 1024 + head * 64) * Nc + nb + q0;
    const float* Kg = qk + ((size_t)b * 1024 + 512 + head * 64) * Nc + nb;
    const float* Vg = v  + ((size_t)b * 512 + head * 64) * Nc + nb;
    float*       Og = ao + ((size_t)b * 512 + head * 64) * Nc + nb + q0;

    for (int t = tid; t < 4096; t += 256) {
        const int d = t >> 6, q = t & 63;
        Qs[t] = Qg[(size_t)d * Nc + q];
    }
    if (tid < 64) { mrow[tid] = -1e30f; lrow[tid] = 0.0f; }

    float acc[4][4] = {};
    const float scale = 0.125f;    // hd^-0.5, hd=64
    const int q = tid & 63, seg = tid >> 6;

    for (int kt = 0; kt < 16; kt++) {
        const int kb = kt * 64;
        __syncthreads();  // protects Ks/Vs/Ps reuse (and Q/m/l init on iter 0)
        for (int t = tid; t < 4096; t += 256) {
            const int d = t >> 6, k = t & 63;
            Ks[t] = Kg[(size_t)d * Nc + kb + k];
            Vs[k * 68 + d] = Vg[(size_t)d * Nc + kb + k];
        }
        __syncthreads();

        // St[k][q] = sum_d K[k][d]*Q[q][d]
        float s[4][4] = {};
        #pragma unroll 8
        for (int d = 0; d < 64; d++) {
            float4 av = *(const float4*)&Ks[d * 64 + ty * 4];
            float4 bv = *(const float4*)&Qs[d * 64 + tx * 4];
            float a[4] = {av.x, av.y, av.z, av.w};
            float c2[4] = {bv.x, bv.y, bv.z, bv.w};
            #pragma unroll
            for (int i = 0; i < 4; i++)
                #pragma unroll
                for (int j = 0; j < 4; j++)
                    s[i][j] += a[i] * c2[j];
        }
        #pragma unroll
        for (int i = 0; i < 4; i++) {
            float4 r = make_float4(s[i][0] * scale, s[i][1] * scale,
                                   s[i][2] * scale, s[i][3] * scale);
            *(float4*)&Ps[(ty * 4 + i) * 68 + tx * 4] = r;
        }
        __syncthreads();

        // per-q max over this tile
        float lm = -1e30f;
        #pragma unroll
        for (int kk = 0; kk < 16; kk++)
            lm = fmaxf(lm, Ps[(seg * 16 + kk) * 68 + q]);
        red[seg * 64 + q] = lm;
        __syncthreads();
        if (tid < 64) {
            const float tm = fmaxf(fmaxf(red[tid], red[64 + tid]),
                                   fmaxf(red[128 + tid], red[192 + tid]));
            const float mo = mrow[tid];
            const float mn = fmaxf(mo, tm);
            mrow[tid] = mn;
            fac[tid] = __expf(mo - mn);
        }
        __syncthreads();

        // exponentiate + partial sums, rescale accumulator
        const float mq = mrow[q];
        float psum = 0.0f;
        #pragma unroll
        for (int kk = 0; kk < 16; kk++) {
            const int idx = (seg * 16 + kk) * 68 + q;
            const float e = __expf(Ps[idx] - mq);
            Ps[idx] = e;
            psum += e;
        }
        red[seg * 64 + q] = psum;
        #pragma unroll
        for (int i = 0; i < 4; i++) {
            const float f = fac[ty * 4 + i];
            #pragma unroll
            for (int j = 0; j < 4; j++) acc[i][j] *= f;
        }
        __syncthreads();
        if (tid < 64)
            lrow[tid] = lrow[tid] * fac[tid] +
                        red[tid] + red[64 + tid] + red[128 + tid] + red[192 + tid];

        // acc[q][dv] += P[k][q] * V[k][dv]
        #pragma unroll 4
        for (int k = 0; k < 64; k++) {
            float4 av = *(const float4*)&Ps[k * 68 + ty * 4];
            float4 bv = *(const float4*)&Vs[k * 68 + tx * 4];
            float a[4] = {av.x, av.y, av.z, av.w};
            float c2[4] = {bv.x, bv.y, bv.z, bv.w};
            #pragma unroll
            for (int i = 0; i < 4; i++)
                #pragma unroll
                for (int j = 0; j < 4; j++)
                    acc[i][j] += a[i] * c2[j];
        }
    }
    __syncthreads();

    // normalize, stage transposed [dv][q] for coalesced channel-major store
    float* Os = Ps;  // 64*65 fits in Ps region
    float linv[4];
    #pragma unroll
    for (int i = 0; i < 4; i++) linv[i] = 1.0f / lrow[ty * 4 + i];
    #pragma unroll
    for (int i = 0; i < 4; i++)
        #pragma unroll
        for (int j = 0; j < 4; j++)
            Os[(tx * 4 + j) * 65 + ty * 4 + i] = acc[i][j] * linv[i];
    __syncthreads();
    for (int t = tid; t < 4096; t += 256) {
        const int dv = t >> 6, qq = t & 63;
        Og[(size_t)dv * Nc + qq] = Os[dv * 65 + qq];
    }
}

// ---------------------------------------------------------------------------
extern "C" void kernel_launch(void* const* d_in, const int* in_sizes, int n_in,
                              void* d_out, int out_size)
{
    const float* x     = (const float*)d_in[0];
    const float* qk_w  = (const float*)d_in[1];
    const float* qk_g  = (const float*)d_in[2];
    const float* qk_b  = (const float*)d_in[3];
    const float* qk_rm = (const float*)d_in[4];
    const float* qk_rv = (const float*)d_in[5];
    const float* v_w   = (const float*)d_in[6];
    const float* v_g   = (const float*)d_in[7];
    const float* v_b   = (const float*)d_in[8];
    const float* v_rm  = (const float*)d_in[9];
    const float* v_rv  = (const float*)d_in[10];
    const float* pe_w  = (const float*)d_in[11];
    const float* pe_g  = (const float*)d_in[12];
    const float* pe_b  = (const float*)d_in[13];
    const float* pe_rm = (const float*)d_in[14];
    const float* pe_rv = (const float*)d_in[15];
    const float* pr_w  = (const float*)d_in[16];
    const float* pr_g  = (const float*)d_in[17];
    const float* pr_b  = (const float*)d_in[18];
    const float* pr_rm = (const float*)d_in[19];
    const float* pr_rv = (const float*)d_in[20];

    float *qkb, *vb, *ppb, *aob;
    cudaGetSymbolAddress((void**)&qkb, g_qk);
    cudaGetSymbolAddress((void**)&vb,  g_v);
    cudaGetSymbolAddress((void**)&ppb, g_pp);
    cudaGetSymbolAddress((void**)&aob, g_ao);

    cudaFuncSetAttribute(attn_kernel,
                         cudaFuncAttributeMaxDynamicSharedMemorySize, 69376);

    // 1) qk = silu(bn(qk_w @ x))
    gemm_bnsilu<<<dim3(64, 16, 8), 256>>>(qk_w, x, nullptr,
        qk_g, qk_b, qk_rm, qk_rv, qkb, 1024, Cc, Nc);
    // 2) v = silu(bn(v_w @ x))
    gemm_bnsilu<<<dim3(64, 8, 8), 256>>>(v_w, x, nullptr,
        v_g, v_b, v_rm, v_rv, vb, 512, Cc, Nc);
    // 3) pp = silu(bn(conv3x3(v)))
    conv3x3_bnsilu<<<dim3(8, 64, 8), 256>>>(vb, pe_w,
        pe_g, pe_b, pe_rm, pe_rv, ppb);
    // 4) attention
    attn_kernel<<<dim3(16, 256), 256, 69376>>>(qkb, vb, aob);
    // 5) y = silu(bn(pr_w @ (ao + pp)))
    gemm_bnsilu<<<dim3(64, 8, 8), 256>>>(pr_w, aob, ppb,
        pr_g, pr_b, pr_rm, pr_rv, (float*)d_out, 512, Cc, Nc);
}